// round 9
// baseline (speedup 1.0000x reference)
#include <cuda_runtime.h>
#include <cstdint>

#define NFEAT 784
#define NCLS  10
#define KC    16
#define NT    49                     // 784 / 16
#define TPB   224                    // 7 warps
#define NWARP 7
#define RPT   2
#define ROWSPW 64                    // rows per warp
#define ROWSPC (NWARP * ROWSPW)      // 448 rows per CTA -> grid 147
#define XSTR  20                     // 16 + 4 pad: conflict-free LDS.128
#define NBUF  4                      // warp-private ring depth (R5)
#define RINGF (NBUF * ROWSPW * XSTR)               // 5120 floats per warp
#define XS_FLOATS (NWARP * RINGF)                  // 35840
#define AS_FLOATS (NCLS * NFEAT)                   // 7840
#define RED_FLOATS (NWARP * NCLS)                  // 70
#define SMEM_FLOATS (XS_FLOATS + AS_FLOATS + RED_FLOATS + 2)
#define SMEM_BYTES  (SMEM_FLOATS * 4)              // ~174.8 KB -> 1 CTA/SM

// ---------------------------------------------------------------------------
__device__ __forceinline__ void cp_async16(uint32_t saddr, const void* gptr) {
    asm volatile("cp.async.cg.shared.global [%0], [%1], 16;\n"
                 :: "r"(saddr), "l"(gptr));
}
#define CP_COMMIT() asm volatile("cp.async.commit_group;\n" ::: "memory")
#define CP_WAIT(n)  asm volatile("cp.async.wait_group %0;\n" :: "n"(n) : "memory")
#define FMA_F32X2(d, a, b) \
    asm volatile("fma.rn.f32x2 %0, %1, %2, %0;" : "+l"(d) : "l"(a), "l"(b))

extern __shared__ float smem[];

// Warp-private stage of tile t: 64 rows x 16 k, 8 chunks/lane, one group.
__device__ __forceinline__ void issue_tile(const float* __restrict__ x,
                                           float* xw, int wrow0, int Brows,
                                           int lane, int t) {
    const int k0 = t * KC;
    float* xb = xw + (t & (NBUF - 1)) * (ROWSPW * XSTR);
#pragma unroll
    for (int i = 0; i < 8; ++i) {
        int g  = lane + i * 32;        // 0..255: (row, 16B-chunk)
        int r  = g >> 2;
        int ch = g & 3;
        int row = wrow0 + r;
        if (row >= Brows) row = Brows - 1;   // clamp (reads discarded)
        const float* gp = x + (size_t)row * NFEAT + k0 + ch * 4;
        uint32_t sa = (uint32_t)__cvta_generic_to_shared(xb + r * XSTR + ch * 4);
        cp_async16(sa, gp);
    }
    CP_COMMIT();
}

// ---------------------------------------------------------------------------
// R5 structure, ILP-restructured consumer: per-CTA fold of sparse+FC into
// A[10,784] (shared broadcast), each warp independently streams its own 64
// rows through a private 4-deep cp.async ring. Per half-tile: ALL 24 LDS.128
// batched into registers, THEN 80 packed FFMA2. Barrier-free mainloop.
// ---------------------------------------------------------------------------
__global__ void __launch_bounds__(TPB, 1)
fused_kernel(const float* __restrict__ x,
             const float* __restrict__ W,
             const float* __restrict__ Bsp,
             const float* __restrict__ fcw,
             const float* __restrict__ fcb,
             float* __restrict__ out, int Brows)
{
    float* As  = smem + XS_FLOATS;            // [10][784]
    float* red = As + AS_FLOATS;              // [7][10]

    const int tid  = threadIdx.x;
    const int wid  = tid >> 5;
    const int lane = tid & 31;
    const int wrow0 = blockIdx.x * ROWSPC + wid * ROWSPW;
    float* xw = smem + wid * RINGF;

    // Kick DRAM immediately: 3 tiles in flight per warp while A is built.
    issue_tile(x, xw, wrow0, Brows, lane, 0);
    issue_tile(x, xw, wrow0, Brows, lane, 1);
    issue_tile(x, xw, wrow0, Brows, lane, 2);

    // ---- build A and per-warp bias partials in shared ----
    float part[NCLS];
#pragma unroll
    for (int c = 0; c < NCLS; ++c) part[c] = 0.f;

    for (int k = tid; k < NFEAT; k += TPB) {
        // scatter column map (faithful to the reference's i=782 wraparound bug)
        int c0i = (k == NFEAT - 2) ? 0 : k;
        int c1i = (k == NFEAT - 2) ? 1 : ((k + 1 == NFEAT) ? 0 : k + 1);
        float w0 = W[2*k],   w1 = W[2*k+1];
        float b0 = Bsp[2*k], b1 = Bsp[2*k+1];
#pragma unroll
        for (int c = 0; c < NCLS; ++c) {
            float f0 = __ldg(fcw + c * NFEAT + c0i);
            float f1 = __ldg(fcw + c * NFEAT + c1i);
            As[c * NFEAT + k] = f0 * w0 + f1 * w1;
            part[c] += f0 * b0 + f1 * b1;
        }
    }
#pragma unroll
    for (int off = 16; off; off >>= 1)
#pragma unroll
        for (int c = 0; c < NCLS; ++c)
            part[c] += __shfl_down_sync(0xffffffffu, part[c], off);
    if (lane == 0)
#pragma unroll
        for (int c = 0; c < NCLS; ++c) red[wid * NCLS + c] = part[c];
    __syncthreads();     // the ONLY barrier: A + red visible to all warps

    // ---- barrier-free main GEMV loop: 2 rows/thread, batched loads ----
    unsigned long long acc0[NCLS], acc1[NCLS];
#pragma unroll
    for (int c = 0; c < NCLS; ++c) { acc0[c] = 0ULL; acc1[c] = 0ULL; }

    const float* Aptr = As;
    for (int t = 0; t < NT; ++t) {
        if (t < NT - 2)       { CP_WAIT(2); }
        else if (t == NT - 2) { CP_WAIT(1); }
        else                  { CP_WAIT(0); }

        const float* xb  = xw + (t & (NBUF - 1)) * (ROWSPW * XSTR);
        const float* xr0 = xb + lane * XSTR;
        const float* xr1 = xb + (32 + lane) * XSTR;

#pragma unroll
        for (int h = 0; h < 2; ++h) {            // two half-tiles of 8 k
            // --- load phase: 4 x-vectors + 20 A-vectors, all batched ---
            ulonglong2 xa0 = *(const ulonglong2*)(xr0 + 8 * h);
            ulonglong2 xb0 = *(const ulonglong2*)(xr0 + 8 * h + 4);
            ulonglong2 xa1 = *(const ulonglong2*)(xr1 + 8 * h);
            ulonglong2 xb1 = *(const ulonglong2*)(xr1 + 8 * h + 4);
            ulonglong2 av0[NCLS], av1[NCLS];
#pragma unroll
            for (int c = 0; c < NCLS; ++c) {
                av0[c] = *(const ulonglong2*)(Aptr + c * NFEAT + 8 * h);
                av1[c] = *(const ulonglong2*)(Aptr + c * NFEAT + 8 * h + 4);
            }
            // --- compute phase: 80 packed FFMA2, all operands resident ---
#pragma unroll
            for (int c = 0; c < NCLS; ++c) {
                FMA_F32X2(acc0[c], xa0.x, av0[c].x);
                FMA_F32X2(acc0[c], xa0.y, av0[c].y);
                FMA_F32X2(acc1[c], xa1.x, av0[c].x);
                FMA_F32X2(acc1[c], xa1.y, av0[c].y);
                FMA_F32X2(acc0[c], xb0.x, av1[c].x);
                FMA_F32X2(acc0[c], xb0.y, av1[c].y);
                FMA_F32X2(acc1[c], xb1.x, av1[c].x);
                FMA_F32X2(acc1[c], xb1.y, av1[c].y);
            }
        }
        Aptr += KC;
        if (t + 3 < NT) issue_tile(x, xw, wrow0, Brows, lane, t + 3);
    }

    // ---- epilogue: bias from red (broadcast reads), softmax, store ----
    float c0v[NCLS];
#pragma unroll
    for (int c = 0; c < NCLS; ++c) {
        float s = __ldg(fcb + c);
#pragma unroll
        for (int w = 0; w < NWARP; ++w) s += red[w * NCLS + c];
        c0v[c] = s;
    }

#pragma unroll
    for (int rsel = 0; rsel < RPT; ++rsel) {
        const unsigned long long* acc = rsel ? acc1 : acc0;
        float logit[NCLS];
#pragma unroll
        for (int c = 0; c < NCLS; ++c) {
            float lo = __uint_as_float((unsigned)(acc[c] & 0xffffffffu));
            float hi = __uint_as_float((unsigned)(acc[c] >> 32));
            logit[c] = lo + hi + c0v[c];
        }
        float m = logit[0];
#pragma unroll
        for (int c = 1; c < NCLS; ++c) m = fmaxf(m, logit[c]);
        float ssum = 0.f;
#pragma unroll
        for (int c = 0; c < NCLS; ++c) { logit[c] = __expf(logit[c] - m); ssum += logit[c]; }
        float inv = 1.0f / ssum;

        const int row = wrow0 + lane + rsel * 32;
        if (row < Brows) {
            float2* po = (float2*)(out + (size_t)row * NCLS);
#pragma unroll
            for (int c = 0; c < NCLS; c += 2)
                po[c >> 1] = make_float2(logit[c] * inv, logit[c + 1] * inv);
        }
    }
}

// ---------------------------------------------------------------------------
extern "C" void kernel_launch(void* const* d_in, const int* in_sizes, int n_in,
                              void* d_out, int out_size) {
    const float* x   = (const float*)d_in[0];
    const float* W   = (const float*)d_in[1];
    const float* bsp = (const float*)d_in[2];
    const float* fcw = (const float*)d_in[3];
    const float* fcb = (const float*)d_in[4];
    float* out = (float*)d_out;
    const int Brows = in_sizes[0] / NFEAT;

    cudaFuncSetAttribute(fused_kernel,
                         cudaFuncAttributeMaxDynamicSharedMemorySize, SMEM_BYTES);

    const int grid = (Brows + ROWSPC - 1) / ROWSPC;   // 147 for B=65536
    fused_kernel<<<grid, TPB, SMEM_BYTES>>>(x, W, bsp, fcw, fcb, out, Brows);
}